// round 9
// baseline (speedup 1.0000x reference)
#include <cuda_runtime.h>
#include <cuda_fp16.h>
#include <math.h>
#include <cstdint>

// Problem constants
#define BB 4
#define LL 1024
#define DD 512
#define NN 16
#define OUTD 512
#define NLAYER 2
#define NCH 32
#define LCH 32

#define BLD (BB*LL*DD)
#define BLN (BB*LL*NN)
#define CHN (BB*NCH*DD*NN)

#define MM (BB*LL)      // 4096 rows
#define KC 1536         // concatenated K (3x512): [hi|lo|hi] x [hi|hi|lo]
#define NW 576          // widened N for fused dt+B+C gemm

// Scratch
__device__ float g_y[BLD];
__device__ float g_dt[BLD];
__device__ float g_Bm[BLN];
__device__ float g_Cm[BLN];
__device__ float g_P[CHN];
__device__ float g_He[CHN];
__device__ float g_carry[CHN];
__device__ __half g_Xcat0[(size_t)MM * KC];       // [Xh | Xl | Xh]
__device__ __half g_Xcat1[(size_t)MM * KC];       // z split
__device__ __half g_Wcat[5 * (size_t)NW * KC];    // [hi|hi|lo], transposed, 576-row slots

__device__ __forceinline__ float softplusf(float x) {
    return fmaxf(x, 0.f) + log1pf(__expf(-fabsf(x)));
}

__device__ __forceinline__ uint32_t smem_u32(const void* p) {
    uint32_t a;
    asm("{ .reg .u64 t; cvta.to.shared.u64 t, %1; cvt.u32.u64 %0, t; }" : "=r"(a) : "l"(p));
    return a;
}

// swizzled byte offset inside a 128B-row tile: r = row, c = 16B chunk in [0,8)
__device__ __forceinline__ uint32_t swz(int r, int c) {
    return ((uint32_t)r << 7) + ((uint32_t)(c ^ (r & 7)) << 4);
}

// ---------------------------------------------------------------------------
// fp16-input, fp32-acc HMMA GEMM. 512 threads (16 warps: 4M x 4N, warp tile
// 32x16), tile 128(M) x 64(N), BK=64, 3-stage cp.async, 2 CTA/SM -> 32 warps/SM.
// C[M=4096, Ncols] = Xcat[M, KC] @ Wcat[Ncols, KC]^T  (TN)
// EPI 0: bias (N=512)                  grid (8, 32)
// EPI 1: dt softplus + Bm/Cm fused     grid (9, 32)
// EPI 2: bias + fp16-split to xout     grid (8, 32)
// ---------------------------------------------------------------------------
#define BK 64
#define STG 3
#define ABYTES 16384
#define BBYTES 8192
#define STAGE_BYTES (ABYTES + BBYTES)
#define TC_SMEM (STG * STAGE_BYTES)

template<int EPI>
__global__ void __launch_bounds__(512, 2)
tc_gemm(const __half* __restrict__ A, const __half* __restrict__ Bw,
        const float* __restrict__ bias, const float* __restrict__ bB,
        const float* __restrict__ bC, float* __restrict__ C,
        __half* __restrict__ xout)
{
    extern __shared__ char smem[];
    uint32_t sbase = smem_u32(smem);

    int tid = threadIdx.x, wid = tid >> 5, lane = tid & 31;
    int bn = blockIdx.x * 64, bm = blockIdx.y * 128;
    int wm = wid & 3;           // m offset wm*32
    int wn = wid >> 2;          // n offset wn*16 (0..3)

    int lrow = ((lane >> 3) & 1) * 8 + (lane & 7);
    int lck = lane >> 4;        // 0..1

    // ldmatrix row bases (swizzle chunk computed per use)
    uint32_t abase[2], asel[2];
    #pragma unroll
    for (int mt = 0; mt < 2; mt++) {
        int r = wm * 32 + mt * 16 + lrow;
        abase[mt] = (uint32_t)r << 7;
        asel[mt] = r & 7;
    }
    uint32_t bbase, bsel;
    {
        int r = wn * 16 + lrow;
        bbase = ((uint32_t)r << 7) + ABYTES;
        bsel = r & 7;
    }

    // cp.async mapping: A 1024 chunks (2/thread), B 512 chunks (1/thread)
    int ra = tid >> 2, ca0 = (tid & 3) * 2;
    int rb = tid >> 3, cb0 = tid & 7;
    const __half* gA = A + (size_t)(bm + ra) * KC + ca0 * 8;
    const __half* gB = Bw + (size_t)(bn + rb) * KC + cb0 * 8;
    uint32_t dA0 = swz(ra, ca0), dA1 = swz(ra, ca0 + 1);
    uint32_t dB0 = ABYTES + swz(rb, cb0);

    float acc[2][2][4];
    #pragma unroll
    for (int i = 0; i < 2; i++)
        #pragma unroll
        for (int j = 0; j < 2; j++)
            #pragma unroll
            for (int q = 0; q < 4; q++) acc[i][j][q] = 0.f;

    const int NKB = KC / BK;    // 24

    #pragma unroll
    for (int s = 0; s < STG - 1; s++) {
        uint32_t st = sbase + s * STAGE_BYTES;
        int ko = s * BK;
        asm volatile("cp.async.cg.shared.global [%0], [%1], 16;" :: "r"(st + dA0), "l"(gA + ko));
        asm volatile("cp.async.cg.shared.global [%0], [%1], 16;" :: "r"(st + dA1), "l"(gA + ko + 8));
        asm volatile("cp.async.cg.shared.global [%0], [%1], 16;" :: "r"(st + dB0), "l"(gB + ko));
        asm volatile("cp.async.commit_group;" ::: "memory");
    }

    int sbuf = 0;
    for (int kb = 0; kb < NKB; kb++) {
        asm volatile("cp.async.wait_group %0;" :: "n"(STG - 2) : "memory");
        __syncthreads();

        int knext = kb + STG - 1;
        if (knext < NKB) {
            int sn = knext % STG;
            uint32_t st = sbase + sn * STAGE_BYTES;
            int ko = knext * BK;
            asm volatile("cp.async.cg.shared.global [%0], [%1], 16;" :: "r"(st + dA0), "l"(gA + ko));
            asm volatile("cp.async.cg.shared.global [%0], [%1], 16;" :: "r"(st + dA1), "l"(gA + ko + 8));
            asm volatile("cp.async.cg.shared.global [%0], [%1], 16;" :: "r"(st + dB0), "l"(gB + ko));
        }
        asm volatile("cp.async.commit_group;" ::: "memory");

        uint32_t st = sbase + sbuf * STAGE_BYTES;

        #pragma unroll
        for (int ks = 0; ks < 4; ks++) {
            int ac = ks * 2 + lck;
            uint32_t bufA[2][4], bufB[4];
            #pragma unroll
            for (int mt = 0; mt < 2; mt++) {
                uint32_t ao = st + abase[mt] + (uint32_t)((ac ^ asel[mt]) << 4);
                asm volatile("ldmatrix.sync.aligned.m8n8.x4.shared.b16 {%0,%1,%2,%3}, [%4];"
                             : "=r"(bufA[mt][0]), "=r"(bufA[mt][1]),
                               "=r"(bufA[mt][2]), "=r"(bufA[mt][3])
                             : "r"(ao));
            }
            {
                uint32_t bo = st + bbase + (uint32_t)((ac ^ bsel) << 4);
                asm volatile("ldmatrix.sync.aligned.m8n8.x4.shared.b16 {%0,%1,%2,%3}, [%4];"
                             : "=r"(bufB[0]), "=r"(bufB[1]), "=r"(bufB[2]), "=r"(bufB[3])
                             : "r"(bo));
            }
            #pragma unroll
            for (int mt = 0; mt < 2; mt++)
                #pragma unroll
                for (int nf = 0; nf < 2; nf++)
                    asm volatile(
                        "mma.sync.aligned.m16n8k16.row.col.f32.f16.f16.f32 "
                        "{%0,%1,%2,%3}, {%4,%5,%6,%7}, {%8,%9}, {%0,%1,%2,%3};"
                        : "+f"(acc[mt][nf][0]), "+f"(acc[mt][nf][1]),
                          "+f"(acc[mt][nf][2]), "+f"(acc[mt][nf][3])
                        : "r"(bufA[mt][0]), "r"(bufA[mt][1]),
                          "r"(bufA[mt][2]), "r"(bufA[mt][3]),
                          "r"(bufB[nf]), "r"(bufB[2 + nf]));
        }
        sbuf++;
        if (sbuf == STG) sbuf = 0;
    }

    // epilogue
    int mbase = bm + wm * 32 + (lane >> 2);
    int nbase = bn + wn * 16 + (lane & 3) * 2;
    #pragma unroll
    for (int mt = 0; mt < 2; mt++) {
        #pragma unroll
        for (int nf = 0; nf < 2; nf++) {
            int col = nbase + nf * 8;
            int m0 = mbase + mt * 16;
            float b0, b1;
            if (EPI == 1 && col >= 512) {
                if (col < 528)      { b0 = bB[col - 512]; b1 = bB[col - 511]; }
                else if (col < 544) { b0 = bC[col - 528]; b1 = bC[col - 527]; }
                else                { b0 = 0.f; b1 = 0.f; }
            } else {
                b0 = bias[col]; b1 = bias[col + 1];
            }
            float v0 = acc[mt][nf][0] + b0, v1 = acc[mt][nf][1] + b1;
            float v2 = acc[mt][nf][2] + b0, v3 = acc[mt][nf][3] + b1;

            if (EPI == 1 && col >= 512) {
                if (col < 528) {
                    int n = col - 512;
                    *(float2*)(g_Bm + (size_t)m0 * NN + n)       = make_float2(v0, v1);
                    *(float2*)(g_Bm + (size_t)(m0 + 8) * NN + n) = make_float2(v2, v3);
                } else if (col < 544) {
                    int n = col - 528;
                    *(float2*)(g_Cm + (size_t)m0 * NN + n)       = make_float2(v0, v1);
                    *(float2*)(g_Cm + (size_t)(m0 + 8) * NN + n) = make_float2(v2, v3);
                }
                continue;
            }
            if (EPI == 1) { v0 = softplusf(v0); v1 = softplusf(v1); v2 = softplusf(v2); v3 = softplusf(v3); }
            *(float2*)(C + (size_t)m0 * DD + col)       = make_float2(v0, v1);
            *(float2*)(C + (size_t)(m0 + 8) * DD + col) = make_float2(v2, v3);
            if (EPI == 2) {
                __half h0 = __float2half_rn(v0), h1 = __float2half_rn(v1);
                __half h2 = __float2half_rn(v2), h3 = __float2half_rn(v3);
                __half2 hv0(h0, h1), hv1(h2, h3);
                __half2 lv0(__float2half_rn(v0 - __half2float(h0)),
                            __float2half_rn(v1 - __half2float(h1)));
                __half2 lv1(__float2half_rn(v2 - __half2float(h2)),
                            __float2half_rn(v3 - __half2float(h3)));
                __half* r0 = xout + (size_t)m0 * KC + col;
                __half* r1 = xout + (size_t)(m0 + 8) * KC + col;
                *(__half2*)(r0)        = hv0;
                *(__half2*)(r0 + 512)  = lv0;
                *(__half2*)(r0 + 1024) = hv0;
                *(__half2*)(r1)        = hv1;
                *(__half2*)(r1 + 512)  = lv1;
                *(__half2*)(r1 + 1024) = hv1;
            }
        }
    }
}

// ---------------------------------------------------------------------------
// Activation split (x only): float -> Xcat0 fp16 [hi|lo|hi]
// ---------------------------------------------------------------------------
__global__ void splitx_k(const float4* __restrict__ in)
{
    int i = blockIdx.x * blockDim.x + threadIdx.x;
    int m = i >> 7;
    int k4 = (i & 127) << 2;
    float4 v = in[i];
    __half2 h0(__float2half_rn(v.x), __float2half_rn(v.y));
    __half2 h1(__float2half_rn(v.z), __float2half_rn(v.w));
    __half2 l0(__float2half_rn(v.x - __half2float(h0.x)),
               __float2half_rn(v.y - __half2float(h0.y)));
    __half2 l1(__float2half_rn(v.z - __half2float(h1.x)),
               __float2half_rn(v.w - __half2float(h1.y)));
    __half* row = g_Xcat0 + (size_t)m * KC;
    *(__half2*)(row + k4)        = h0;
    *(__half2*)(row + k4 + 2)    = h1;
    *(__half2*)(row + k4 + 512)  = l0;
    *(__half2*)(row + k4 + 514)  = l1;
    *(__half2*)(row + k4 + 1024) = h0;
    *(__half2*)(row + k4 + 1026) = h1;
}

// ---------------------------------------------------------------------------
// Big-weight transpose+split. blockIdx.z = slot.
// ---------------------------------------------------------------------------
__global__ void tsplit_all_k(const float* __restrict__ Wdt, const float* __restrict__ Wlin,
                             const float* __restrict__ Wdec)
{
    __shared__ float t[32][33];
    int slot = blockIdx.z;
    const float* W = (slot == 0) ? Wdt
                   : (slot == 1) ? Wdt + (size_t)DD * DD
                   : (slot == 2) ? Wlin
                   : (slot == 3) ? Wlin + (size_t)DD * DD
                                 : Wdec;
    __half* out = g_Wcat + (size_t)slot * NW * KC;

    int bk = blockIdx.x * 32, bn = blockIdx.y * 32;
    int tx = threadIdx.x, ty = threadIdx.y;
    #pragma unroll
    for (int i = 0; i < 32; i += 8)
        t[ty + i][tx] = W[(size_t)(bk + ty + i) * DD + bn + tx];
    __syncthreads();
    #pragma unroll
    for (int i = 0; i < 32; i += 8) {
        float v = t[tx][ty + i];
        __half h = __float2half_rn(v);
        __half l = __float2half_rn(v - __half2float(h));
        size_t o = (size_t)(bn + ty + i) * KC + bk + tx;
        out[o]        = h;
        out[o + 512]  = h;
        out[o + 1024] = l;
    }
}

// ---------------------------------------------------------------------------
// WB/WC transpose+split into rows 512..575 of dt slots.
// ---------------------------------------------------------------------------
__global__ void tsplit_bc_k(const float* __restrict__ WB, const float* __restrict__ WC)
{
    int l = blockIdx.y;
    int bk = blockIdx.x * 32;
    int tx = threadIdx.x;
    __half* out = g_Wcat + (size_t)l * NW * KC + (size_t)512 * KC;

    for (int r = threadIdx.y; r < 64; r += 8) {
        float v = 0.f;
        if (r < 16)      v = WB[(size_t)l * DD * NN + (size_t)(bk + tx) * NN + r];
        else if (r < 32) v = WC[(size_t)l * DD * NN + (size_t)(bk + tx) * NN + (r - 16)];
        __half h = __float2half_rn(v);
        __half lo = __float2half_rn(v - __half2float(h));
        size_t o = (size_t)r * KC + bk + tx;
        out[o]        = h;
        out[o + 512]  = h;
        out[o + 1024] = lo;
    }
}

// ---------------------------------------------------------------------------
// Scan pass 1: local chunk scan from zero; store P, He.
// grid = (4, NCH, 4), block 128
// ---------------------------------------------------------------------------
__global__ void scan1_k(const float* __restrict__ yin, const float* __restrict__ A)
{
    __shared__ float sB[LCH * NN];
    int d = blockIdx.x * 128 + threadIdx.x;
    int c = blockIdx.y, b = blockIdx.z;
    int t0 = c * LCH;

    const float4* src = (const float4*)(g_Bm + ((size_t)b * LL + t0) * NN);
    #pragma unroll
    for (int i = threadIdx.x; i < LCH * NN / 4; i += 128)
        ((float4*)sB)[i] = src[i];
    __syncthreads();

    float av[NN], h[NN], p[NN];
    #pragma unroll
    for (int q = 0; q < 4; q++)
        *(float4*)(av + q * 4) = *(const float4*)(A + (size_t)d * NN + q * 4);
    #pragma unroll
    for (int n = 0; n < NN; n++) { h[n] = 0.f; p[n] = 1.f; }

    const float* dtp = g_dt + ((size_t)b * LL + t0) * DD + d;
    const float* yp  = yin  + ((size_t)b * LL + t0) * DD + d;

    for (int t = 0; t < LCH; t++) {
        float dv = dtp[(size_t)t * DD];
        float u  = dv * yp[(size_t)t * DD];
        #pragma unroll
        for (int n = 0; n < NN; n++) {
            float e = __expf(dv * av[n]);
            p[n] *= e;
            h[n] = fmaf(e, h[n], u * sB[t * NN + n]);
        }
    }

    size_t o = (((size_t)b * NCH + c) * DD + d) * NN;
    #pragma unroll
    for (int q = 0; q < 4; q++) {
        *(float4*)(g_P  + o + q * 4) = *(float4*)(p + q * 4);
        *(float4*)(g_He + o + q * 4) = *(float4*)(h + q * 4);
    }
}

// ---------------------------------------------------------------------------
// Scan pass 2 (batched loads across NCH chunks)
// ---------------------------------------------------------------------------
__global__ void scan2_k()
{
    int tid = blockIdx.x * blockDim.x + threadIdx.x;
    int b  = tid >> 13;
    int dn = tid & 8191;
    size_t base = (size_t)b * NCH * DD * NN + dn;

    float p[NCH], he[NCH];
    #pragma unroll
    for (int c = 0; c < NCH; c++) {
        p[c]  = g_P [base + (size_t)c * DD * NN];
        he[c] = g_He[base + (size_t)c * DD * NN];
    }
    float hc = 0.f;
    float cr[NCH];
    #pragma unroll
    for (int c = 0; c < NCH; c++) {
        cr[c] = hc;
        hc = fmaf(p[c], hc, he[c]);
    }
    #pragma unroll
    for (int c = 0; c < NCH; c++)
        g_carry[base + (size_t)c * DD * NN] = cr[c];
}

// ---------------------------------------------------------------------------
// Scan pass 3: rescan with carry; write z as fp16 split into Xcat1.
// grid = (4, NCH, 4), block 128
// ---------------------------------------------------------------------------
__global__ void scan3_k(const float* __restrict__ yin, const float* __restrict__ A,
                        const float* __restrict__ Dskip)
{
    __shared__ float sB[LCH * NN];
    __shared__ float sC[LCH * NN];
    int d = blockIdx.x * 128 + threadIdx.x;
    int c = blockIdx.y, b = blockIdx.z;
    int t0 = c * LCH;

    {
        const float4* srcB = (const float4*)(g_Bm + ((size_t)b * LL + t0) * NN);
        const float4* srcC = (const float4*)(g_Cm + ((size_t)b * LL + t0) * NN);
        #pragma unroll
        for (int i = threadIdx.x; i < LCH * NN / 4; i += 128) {
            ((float4*)sB)[i] = srcB[i];
            ((float4*)sC)[i] = srcC[i];
        }
    }
    __syncthreads();

    float av[NN], h[NN];
    #pragma unroll
    for (int q = 0; q < 4; q++)
        *(float4*)(av + q * 4) = *(const float4*)(A + (size_t)d * NN + q * 4);
    size_t co = (((size_t)b * NCH + c) * DD + d) * NN;
    #pragma unroll
    for (int q = 0; q < 4; q++)
        *(float4*)(h + q * 4) = *(const float4*)(g_carry + co + q * 4);

    float ds = Dskip[d];
    const float* dtp = g_dt + ((size_t)b * LL + t0) * DD + d;
    const float* yp  = yin  + ((size_t)b * LL + t0) * DD + d;
    __half* zb = g_Xcat1 + ((size_t)b * LL + t0) * KC + d;

    for (int t = 0; t < LCH; t++) {
        float dv = dtp[(size_t)t * DD];
        float yv = yp[(size_t)t * DD];
        float u  = dv * yv;
        float acc = 0.f;
        #pragma unroll
        for (int n = 0; n < NN; n++) {
            float e = __expf(dv * av[n]);
            h[n] = fmaf(e, h[n], u * sB[t * NN + n]);
            acc = fmaf(h[n], sC[t * NN + n], acc);
        }
        float z = fmaxf(fmaf(ds, yv, acc), 0.f);
        __half hi = __float2half_rn(z);
        __half lo = __float2half_rn(z - __half2float(hi));
        __half* zr = zb + (size_t)t * KC;
        zr[0]    = hi;
        zr[512]  = lo;
        zr[1024] = hi;
    }
}

// ---------------------------------------------------------------------------
// Host launcher
// ---------------------------------------------------------------------------
extern "C" void kernel_launch(void* const* d_in, const int* in_sizes, int n_in,
                              void* d_out, int out_size)
{
    const float* x     = (const float*)d_in[0];
    const float* A     = (const float*)d_in[1];
    const float* Dskip = (const float*)d_in[2];
    const float* WB    = (const float*)d_in[3];
    const float* bB    = (const float*)d_in[4];
    const float* WC    = (const float*)d_in[5];
    const float* bC    = (const float*)d_in[6];
    const float* Wdt   = (const float*)d_in[7];
    const float* bdt   = (const float*)d_in[8];
    const float* Wlin  = (const float*)d_in[9];
    const float* blin  = (const float*)d_in[10];
    const float* Wdec  = (const float*)d_in[11];
    const float* bdec  = (const float*)d_in[12];
    float* out = (float*)d_out;

    float *py, *pdt;
    __half *px0, *px1, *pwc;
    cudaGetSymbolAddress((void**)&py,  g_y);
    cudaGetSymbolAddress((void**)&pdt, g_dt);
    cudaGetSymbolAddress((void**)&px0, g_Xcat0);
    cudaGetSymbolAddress((void**)&px1, g_Xcat1);
    cudaGetSymbolAddress((void**)&pwc, g_Wcat);

    cudaFuncSetAttribute(tc_gemm<0>, cudaFuncAttributeMaxDynamicSharedMemorySize, TC_SMEM);
    cudaFuncSetAttribute(tc_gemm<1>, cudaFuncAttributeMaxDynamicSharedMemorySize, TC_SMEM);
    cudaFuncSetAttribute(tc_gemm<2>, cudaFuncAttributeMaxDynamicSharedMemorySize, TC_SMEM);

    const size_t WCSZ = (size_t)NW * KC;

    dim3 tgrid(16, 16, 5), tblk(32, 8);
    tsplit_all_k<<<tgrid, tblk>>>(Wdt, Wlin, Wdec);
    tsplit_bc_k<<<dim3(16, 2), tblk>>>(WB, WC);

    dim3 gG1(NW / 64, MM / 128);   // (9, 32) fused dt+BC
    dim3 gG(DD / 64, MM / 128);    // (8, 32)
    dim3 gs(DD / 128, NCH, BB);

    splitx_k<<<(BLD / 4) / 256, 256>>>((const float4*)x);

    const float* cur = x;
    for (int l = 0; l < NLAYER; l++) {
        tc_gemm<1><<<gG1, 512, TC_SMEM>>>(px0, pwc + (size_t)l * WCSZ, bdt + l * DD,
                                          bB + l * NN, bC + l * NN, pdt, nullptr);
        scan1_k<<<gs, 128>>>(cur, A + (size_t)l * DD * NN);
        scan2_k<<<(BB * DD * NN) / 256, 256>>>();
        scan3_k<<<gs, 128>>>(cur, A + (size_t)l * DD * NN, Dskip + l * DD);
        tc_gemm<2><<<gG, 512, TC_SMEM>>>(px1, pwc + (size_t)(2 + l) * WCSZ, blin + l * DD,
                                         nullptr, nullptr, py, px0);
        cur = py;
    }
    tc_gemm<0><<<gG, 512, TC_SMEM>>>(px0, pwc + 4 * WCSZ, bdec, nullptr, nullptr, out, nullptr);
}

// round 10
// speedup vs baseline: 1.3516x; 1.3516x over previous
#include <cuda_runtime.h>
#include <cuda_fp16.h>
#include <math.h>
#include <cstdint>

// Problem constants
#define BB 4
#define LL 1024
#define DD 512
#define NN 16
#define OUTD 512
#define NLAYER 2
#define NCH 32
#define LCH 32

#define BLD (BB*LL*DD)
#define BLN (BB*LL*NN)
#define CHN (BB*NCH*DD*NN)

#define MM (BB*LL)      // 4096 rows
#define KC 1536         // concatenated K (3x512): [hi|lo|hi] x [hi|hi|lo]
#define NW 576          // widened N for fused dt+B+C gemm

// Scratch
__device__ float g_y[BLD];
__device__ float g_dt[BLD];
__device__ float g_Bm[BLN];
__device__ float g_Cm[BLN];
__device__ float g_P[CHN];
__device__ float g_He[CHN];
__device__ float g_carry[CHN];
__device__ float g_beff[DD];                      // fused decoder bias
__device__ float g_bzero[DD];                     // zero bias (zero-initialized)
__device__ __half g_Xcat0[(size_t)MM * KC];       // [Xh | Xl | Xh]
__device__ __half g_Xcat1[(size_t)MM * KC];       // z split
__device__ __half g_Wcat[5 * (size_t)NW * KC];    // [hi|hi|lo], transposed, 576-row slots

__device__ __forceinline__ float softplusf(float x) {
    return fmaxf(x, 0.f) + log1pf(__expf(-fabsf(x)));
}

__device__ __forceinline__ uint32_t smem_u32(const void* p) {
    uint32_t a;
    asm("{ .reg .u64 t; cvta.to.shared.u64 t, %1; cvt.u32.u64 %0, t; }" : "=r"(a) : "l"(p));
    return a;
}

// swizzled byte offset inside a 128B-row tile: r = row, c = 16B chunk in [0,8)
__device__ __forceinline__ uint32_t swz(int r, int c) {
    return ((uint32_t)r << 7) + ((uint32_t)(c ^ (r & 7)) << 4);
}

// ---------------------------------------------------------------------------
// fp16-input, fp32-acc HMMA GEMM (R8 configuration — best known).
// C[M, Ncols] = Xcat[M, KC] @ Wcat[Ncols, KC]^T  (TN)
// Tile 128(M) x 64(N), BK=64, 3-stage cp.async, 256 thr (4M x 2N warps).
// EPI 0: bias                          grid (Ncols/64, M/128)
// EPI 1: dt softplus + Bm/Cm fused     grid (9, 32)
// EPI 2: bias + fp16-split to xout     grid (8, 32)
// ---------------------------------------------------------------------------
#define BK 64
#define STG 3
#define ABYTES 16384
#define BBYTES 8192
#define STAGE_BYTES (ABYTES + BBYTES)
#define TC_SMEM (STG * STAGE_BYTES)

template<int EPI>
__global__ void __launch_bounds__(256, 3)
tc_gemm(const __half* __restrict__ A, const __half* __restrict__ Bw,
        const float* __restrict__ bias, const float* __restrict__ bB,
        const float* __restrict__ bC, float* __restrict__ C,
        __half* __restrict__ xout)
{
    extern __shared__ char smem[];
    uint32_t sbase = smem_u32(smem);

    int tid = threadIdx.x, wid = tid >> 5, lane = tid & 31;
    int bn = blockIdx.x * 64, bm = blockIdx.y * 128;
    int wm = wid & 3;           // m offset wm*32
    int wn = wid >> 2;          // n offset wn*32

    int lrow = ((lane >> 3) & 1) * 8 + (lane & 7);
    int lck = lane >> 4;
    uint32_t aoff[2][4], boff[2][4];
    #pragma unroll
    for (int mt = 0; mt < 2; mt++)
        #pragma unroll
        for (int ks = 0; ks < 4; ks++)
            aoff[mt][ks] = swz(wm * 32 + mt * 16 + lrow, ks * 2 + lck);
    #pragma unroll
    for (int nt = 0; nt < 2; nt++)
        #pragma unroll
        for (int ks = 0; ks < 4; ks++)
            boff[nt][ks] = ABYTES + swz(wn * 32 + nt * 16 + lrow, ks * 2 + lck);

    int ra = tid >> 1, ca0 = (tid & 1) * 4;
    int rb = tid >> 2, cb0 = (tid & 3) * 2;
    const __half* gA = A + (size_t)(bm + ra) * KC + ca0 * 8;
    const __half* gB = Bw + (size_t)(bn + rb) * KC + cb0 * 8;
    uint32_t dA[4], dB[2];
    #pragma unroll
    for (int i = 0; i < 4; i++) dA[i] = swz(ra, ca0 + i);
    #pragma unroll
    for (int i = 0; i < 2; i++) dB[i] = ABYTES + swz(rb, cb0 + i);

    float acc[2][4][4];
    #pragma unroll
    for (int i = 0; i < 2; i++)
        #pragma unroll
        for (int j = 0; j < 4; j++)
            #pragma unroll
            for (int q = 0; q < 4; q++) acc[i][j][q] = 0.f;

    const int NKB = KC / BK;    // 24

    #pragma unroll
    for (int s = 0; s < STG - 1; s++) {
        uint32_t st = sbase + s * STAGE_BYTES;
        int ko = s * BK;
        #pragma unroll
        for (int i = 0; i < 4; i++)
            asm volatile("cp.async.cg.shared.global [%0], [%1], 16;" :: "r"(st + dA[i]), "l"(gA + ko + i * 8));
        #pragma unroll
        for (int i = 0; i < 2; i++)
            asm volatile("cp.async.cg.shared.global [%0], [%1], 16;" :: "r"(st + dB[i]), "l"(gB + ko + i * 8));
        asm volatile("cp.async.commit_group;" ::: "memory");
    }

    uint32_t bufA[2][2][4], bufB[2][2][4];

    int sbuf = 0;
    for (int kb = 0; kb < NKB; kb++) {
        asm volatile("cp.async.wait_group %0;" :: "n"(STG - 2) : "memory");
        __syncthreads();

        int knext = kb + STG - 1;
        if (knext < NKB) {
            int sn = knext % STG;
            uint32_t st = sbase + sn * STAGE_BYTES;
            int ko = knext * BK;
            #pragma unroll
            for (int i = 0; i < 4; i++)
                asm volatile("cp.async.cg.shared.global [%0], [%1], 16;" :: "r"(st + dA[i]), "l"(gA + ko + i * 8));
            #pragma unroll
            for (int i = 0; i < 2; i++)
                asm volatile("cp.async.cg.shared.global [%0], [%1], 16;" :: "r"(st + dB[i]), "l"(gB + ko + i * 8));
        }
        asm volatile("cp.async.commit_group;" ::: "memory");

        uint32_t st = sbase + sbuf * STAGE_BYTES;

        // prime ks=0 operands
        #pragma unroll
        for (int mt = 0; mt < 2; mt++)
            asm volatile("ldmatrix.sync.aligned.m8n8.x4.shared.b16 {%0,%1,%2,%3}, [%4];"
                         : "=r"(bufA[0][mt][0]), "=r"(bufA[0][mt][1]),
                           "=r"(bufA[0][mt][2]), "=r"(bufA[0][mt][3])
                         : "r"(st + aoff[mt][0]));
        #pragma unroll
        for (int nt = 0; nt < 2; nt++)
            asm volatile("ldmatrix.sync.aligned.m8n8.x4.shared.b16 {%0,%1,%2,%3}, [%4];"
                         : "=r"(bufB[0][nt][0]), "=r"(bufB[0][nt][1]),
                           "=r"(bufB[0][nt][2]), "=r"(bufB[0][nt][3])
                         : "r"(st + boff[nt][0]));

        #pragma unroll
        for (int ks = 0; ks < 4; ks++) {
            int cb = ks & 1, nb = cb ^ 1;
            if (ks < 3) {
                #pragma unroll
                for (int mt = 0; mt < 2; mt++)
                    asm volatile("ldmatrix.sync.aligned.m8n8.x4.shared.b16 {%0,%1,%2,%3}, [%4];"
                                 : "=r"(bufA[nb][mt][0]), "=r"(bufA[nb][mt][1]),
                                   "=r"(bufA[nb][mt][2]), "=r"(bufA[nb][mt][3])
                                 : "r"(st + aoff[mt][ks + 1]));
                #pragma unroll
                for (int nt = 0; nt < 2; nt++)
                    asm volatile("ldmatrix.sync.aligned.m8n8.x4.shared.b16 {%0,%1,%2,%3}, [%4];"
                                 : "=r"(bufB[nb][nt][0]), "=r"(bufB[nb][nt][1]),
                                   "=r"(bufB[nb][nt][2]), "=r"(bufB[nb][nt][3])
                                 : "r"(st + boff[nt][ks + 1]));
            }
            #pragma unroll
            for (int mt = 0; mt < 2; mt++)
                #pragma unroll
                for (int nt = 0; nt < 2; nt++)
                    #pragma unroll
                    for (int nf = 0; nf < 2; nf++)
                        asm volatile(
                            "mma.sync.aligned.m16n8k16.row.col.f32.f16.f16.f32 "
                            "{%0,%1,%2,%3}, {%4,%5,%6,%7}, {%8,%9}, {%0,%1,%2,%3};"
                            : "+f"(acc[mt][nt * 2 + nf][0]), "+f"(acc[mt][nt * 2 + nf][1]),
                              "+f"(acc[mt][nt * 2 + nf][2]), "+f"(acc[mt][nt * 2 + nf][3])
                            : "r"(bufA[cb][mt][0]), "r"(bufA[cb][mt][1]),
                              "r"(bufA[cb][mt][2]), "r"(bufA[cb][mt][3]),
                              "r"(bufB[cb][nt][nf]), "r"(bufB[cb][nt][2 + nf]));
        }
        sbuf++;
        if (sbuf == STG) sbuf = 0;
    }

    // epilogue
    int mbase = bm + wm * 32 + (lane >> 2);
    int nbase = bn + wn * 32 + (lane & 3) * 2;
    #pragma unroll
    for (int mt = 0; mt < 2; mt++) {
        #pragma unroll
        for (int jf = 0; jf < 4; jf++) {
            int col = nbase + (jf >> 1) * 16 + (jf & 1) * 8;
            int m0 = mbase + mt * 16;
            float b0, b1;
            if (EPI == 1 && col >= 512) {
                if (col < 528)      { b0 = bB[col - 512]; b1 = bB[col - 511]; }
                else if (col < 544) { b0 = bC[col - 528]; b1 = bC[col - 527]; }
                else                { b0 = 0.f; b1 = 0.f; }
            } else {
                b0 = bias[col]; b1 = bias[col + 1];
            }
            float v0 = acc[mt][jf][0] + b0, v1 = acc[mt][jf][1] + b1;
            float v2 = acc[mt][jf][2] + b0, v3 = acc[mt][jf][3] + b1;

            if (EPI == 1 && col >= 512) {
                if (col < 528) {
                    int n = col - 512;
                    *(float2*)(g_Bm + (size_t)m0 * NN + n)       = make_float2(v0, v1);
                    *(float2*)(g_Bm + (size_t)(m0 + 8) * NN + n) = make_float2(v2, v3);
                } else if (col < 544) {
                    int n = col - 528;
                    *(float2*)(g_Cm + (size_t)m0 * NN + n)       = make_float2(v0, v1);
                    *(float2*)(g_Cm + (size_t)(m0 + 8) * NN + n) = make_float2(v2, v3);
                }
                continue;
            }
            if (EPI == 1) { v0 = softplusf(v0); v1 = softplusf(v1); v2 = softplusf(v2); v3 = softplusf(v3); }
            *(float2*)(C + (size_t)m0 * DD + col)       = make_float2(v0, v1);
            *(float2*)(C + (size_t)(m0 + 8) * DD + col) = make_float2(v2, v3);
            if (EPI == 2) {
                __half h0 = __float2half_rn(v0), h1 = __float2half_rn(v1);
                __half h2 = __float2half_rn(v2), h3 = __float2half_rn(v3);
                __half2 hv0(h0, h1), hv1(h2, h3);
                __half2 lv0(__float2half_rn(v0 - __half2float(h0)),
                            __float2half_rn(v1 - __half2float(h1)));
                __half2 lv1(__float2half_rn(v2 - __half2float(h2)),
                            __float2half_rn(v3 - __half2float(h3)));
                __half* r0 = xout + (size_t)m0 * KC + col;
                __half* r1 = xout + (size_t)(m0 + 8) * KC + col;
                *(__half2*)(r0)        = hv0;
                *(__half2*)(r0 + 512)  = lv0;
                *(__half2*)(r0 + 1024) = hv0;
                *(__half2*)(r1)        = hv1;
                *(__half2*)(r1 + 512)  = lv1;
                *(__half2*)(r1 + 1024) = hv1;
            }
        }
    }
}

// ---------------------------------------------------------------------------
// Activation split: float [M][512] -> out fp16 [M][1536] = [hi|lo|hi]
// ---------------------------------------------------------------------------
__global__ void splitx_k(const float4* __restrict__ in, __half* __restrict__ out)
{
    int i = blockIdx.x * blockDim.x + threadIdx.x;
    int m = i >> 7;
    int k4 = (i & 127) << 2;
    float4 v = in[i];
    __half2 h0(__float2half_rn(v.x), __float2half_rn(v.y));
    __half2 h1(__float2half_rn(v.z), __float2half_rn(v.w));
    __half2 l0(__float2half_rn(v.x - __half2float(h0.x)),
               __float2half_rn(v.y - __half2float(h0.y)));
    __half2 l1(__float2half_rn(v.z - __half2float(h1.x)),
               __float2half_rn(v.w - __half2float(h1.y)));
    __half* row = out + (size_t)m * KC;
    *(__half2*)(row + k4)        = h0;
    *(__half2*)(row + k4 + 2)    = h1;
    *(__half2*)(row + k4 + 512)  = l0;
    *(__half2*)(row + k4 + 514)  = l1;
    *(__half2*)(row + k4 + 1024) = h0;
    *(__half2*)(row + k4 + 1026) = h1;
}

// ---------------------------------------------------------------------------
// Big-weight transpose+split. blockIdx.z = slot.
// slots: 0,1 = Wdt layers; 2 = Wlin layer 0; 3 = (unused here); 4 = Wdec
// ---------------------------------------------------------------------------
__global__ void tsplit_all_k(const float* __restrict__ Wdt, const float* __restrict__ Wlin,
                             const float* __restrict__ Wdec)
{
    __shared__ float t[32][33];
    int slot = blockIdx.z;
    const float* W = (slot == 0) ? Wdt
                   : (slot == 1) ? Wdt + (size_t)DD * DD
                   : (slot == 2) ? Wlin
                   : (slot == 3) ? Wlin + (size_t)DD * DD
                                 : Wdec;
    __half* out = g_Wcat + (size_t)slot * NW * KC;

    int bk = blockIdx.x * 32, bn = blockIdx.y * 32;
    int tx = threadIdx.x, ty = threadIdx.y;
    #pragma unroll
    for (int i = 0; i < 32; i += 8)
        t[ty + i][tx] = W[(size_t)(bk + ty + i) * DD + bn + tx];
    __syncthreads();
    #pragma unroll
    for (int i = 0; i < 32; i += 8) {
        float v = t[tx][ty + i];
        __half h = __float2half_rn(v);
        __half l = __float2half_rn(v - __half2float(h));
        size_t o = (size_t)(bn + ty + i) * KC + bk + tx;
        out[o]        = h;
        out[o + 512]  = h;
        out[o + 1024] = l;
    }
}

// Single-slot transpose+split (for the fused decoder weight F in g_y).
__global__ void tsplit_one_k(const float* __restrict__ W, __half* __restrict__ out)
{
    __shared__ float t[32][33];
    int bk = blockIdx.x * 32, bn = blockIdx.y * 32;
    int tx = threadIdx.x, ty = threadIdx.y;
    #pragma unroll
    for (int i = 0; i < 32; i += 8)
        t[ty + i][tx] = W[(size_t)(bk + ty + i) * DD + bn + tx];
    __syncthreads();
    #pragma unroll
    for (int i = 0; i < 32; i += 8) {
        float v = t[tx][ty + i];
        __half h = __float2half_rn(v);
        __half l = __float2half_rn(v - __half2float(h));
        size_t o = (size_t)(bn + ty + i) * KC + bk + tx;
        out[o]        = h;
        out[o + 512]  = h;
        out[o + 1024] = l;
    }
}

// ---------------------------------------------------------------------------
// WB/WC transpose+split into rows 512..575 of dt slots.
// ---------------------------------------------------------------------------
__global__ void tsplit_bc_k(const float* __restrict__ WB, const float* __restrict__ WC)
{
    int l = blockIdx.y;
    int bk = blockIdx.x * 32;
    int tx = threadIdx.x;
    __half* out = g_Wcat + (size_t)l * NW * KC + (size_t)512 * KC;

    for (int r = threadIdx.y; r < 64; r += 8) {
        float v = 0.f;
        if (r < 16)      v = WB[(size_t)l * DD * NN + (size_t)(bk + tx) * NN + r];
        else if (r < 32) v = WC[(size_t)l * DD * NN + (size_t)(bk + tx) * NN + (r - 16)];
        __half h = __float2half_rn(v);
        __half lo = __float2half_rn(v - __half2float(h));
        size_t o = (size_t)r * KC + bk + tx;
        out[o]        = h;
        out[o + 512]  = h;
        out[o + 1024] = lo;
    }
}

// ---------------------------------------------------------------------------
// Fused decoder bias: beff[o] = bdec[o] + sum_d blin2[d] * Wdec[d][o]
// grid 2, block 256
// ---------------------------------------------------------------------------
__global__ void beff_k(const float* __restrict__ blin2, const float* __restrict__ Wdec,
                       const float* __restrict__ bdec)
{
    int o = blockIdx.x * 256 + threadIdx.x;
    float acc = bdec[o];
    for (int d = 0; d < DD; d++)
        acc = fmaf(blin2[d], Wdec[(size_t)d * DD + o], acc);
    g_beff[o] = acc;
}

// ---------------------------------------------------------------------------
// Scan pass 1: local chunk scan from zero; store P, He.
// grid = (4, NCH, 4), block 128
// ---------------------------------------------------------------------------
__global__ void scan1_k(const float* __restrict__ yin, const float* __restrict__ A)
{
    __shared__ float sB[LCH * NN];
    int d = blockIdx.x * 128 + threadIdx.x;
    int c = blockIdx.y, b = blockIdx.z;
    int t0 = c * LCH;

    const float4* src = (const float4*)(g_Bm + ((size_t)b * LL + t0) * NN);
    #pragma unroll
    for (int i = threadIdx.x; i < LCH * NN / 4; i += 128)
        ((float4*)sB)[i] = src[i];
    __syncthreads();

    float av[NN], h[NN], p[NN];
    #pragma unroll
    for (int q = 0; q < 4; q++)
        *(float4*)(av + q * 4) = *(const float4*)(A + (size_t)d * NN + q * 4);
    #pragma unroll
    for (int n = 0; n < NN; n++) { h[n] = 0.f; p[n] = 1.f; }

    const float* dtp = g_dt + ((size_t)b * LL + t0) * DD + d;
    const float* yp  = yin  + ((size_t)b * LL + t0) * DD + d;

    for (int t = 0; t < LCH; t++) {
        float dv = dtp[(size_t)t * DD];
        float u  = dv * yp[(size_t)t * DD];
        #pragma unroll
        for (int n = 0; n < NN; n++) {
            float e = __expf(dv * av[n]);
            p[n] *= e;
            h[n] = fmaf(e, h[n], u * sB[t * NN + n]);
        }
    }

    size_t o = (((size_t)b * NCH + c) * DD + d) * NN;
    #pragma unroll
    for (int q = 0; q < 4; q++) {
        *(float4*)(g_P  + o + q * 4) = *(float4*)(p + q * 4);
        *(float4*)(g_He + o + q * 4) = *(float4*)(h + q * 4);
    }
}

// ---------------------------------------------------------------------------
// Scan pass 2 (batched loads across NCH chunks)
// ---------------------------------------------------------------------------
__global__ void scan2_k()
{
    int tid = blockIdx.x * blockDim.x + threadIdx.x;
    int b  = tid >> 13;
    int dn = tid & 8191;
    size_t base = (size_t)b * NCH * DD * NN + dn;

    float p[NCH], he[NCH];
    #pragma unroll
    for (int c = 0; c < NCH; c++) {
        p[c]  = g_P [base + (size_t)c * DD * NN];
        he[c] = g_He[base + (size_t)c * DD * NN];
    }
    float hc = 0.f;
    float cr[NCH];
    #pragma unroll
    for (int c = 0; c < NCH; c++) {
        cr[c] = hc;
        hc = fmaf(p[c], hc, he[c]);
    }
    #pragma unroll
    for (int c = 0; c < NCH; c++)
        g_carry[base + (size_t)c * DD * NN] = cr[c];
}

// ---------------------------------------------------------------------------
// Scan pass 3: rescan with carry; write z as fp16 split into Xcat1.
// grid = (4, NCH, 4), block 128
// ---------------------------------------------------------------------------
__global__ void scan3_k(const float* __restrict__ yin, const float* __restrict__ A,
                        const float* __restrict__ Dskip)
{
    __shared__ float sB[LCH * NN];
    __shared__ float sC[LCH * NN];
    int d = blockIdx.x * 128 + threadIdx.x;
    int c = blockIdx.y, b = blockIdx.z;
    int t0 = c * LCH;

    {
        const float4* srcB = (const float4*)(g_Bm + ((size_t)b * LL + t0) * NN);
        const float4* srcC = (const float4*)(g_Cm + ((size_t)b * LL + t0) * NN);
        #pragma unroll
        for (int i = threadIdx.x; i < LCH * NN / 4; i += 128) {
            ((float4*)sB)[i] = srcB[i];
            ((float4*)sC)[i] = srcC[i];
        }
    }
    __syncthreads();

    float av[NN], h[NN];
    #pragma unroll
    for (int q = 0; q < 4; q++)
        *(float4*)(av + q * 4) = *(const float4*)(A + (size_t)d * NN + q * 4);
    size_t co = (((size_t)b * NCH + c) * DD + d) * NN;
    #pragma unroll
    for (int q = 0; q < 4; q++)
        *(float4*)(h + q * 4) = *(const float4*)(g_carry + co + q * 4);

    float ds = Dskip[d];
    const float* dtp = g_dt + ((size_t)b * LL + t0) * DD + d;
    const float* yp  = yin  + ((size_t)b * LL + t0) * DD + d;
    __half* zb = g_Xcat1 + ((size_t)b * LL + t0) * KC + d;

    for (int t = 0; t < LCH; t++) {
        float dv = dtp[(size_t)t * DD];
        float yv = yp[(size_t)t * DD];
        float u  = dv * yv;
        float acc = 0.f;
        #pragma unroll
        for (int n = 0; n < NN; n++) {
            float e = __expf(dv * av[n]);
            h[n] = fmaf(e, h[n], u * sB[t * NN + n]);
            acc = fmaf(h[n], sC[t * NN + n], acc);
        }
        float z = fmaxf(fmaf(ds, yv, acc), 0.f);
        __half hi = __float2half_rn(z);
        __half lo = __float2half_rn(z - __half2float(hi));
        __half* zr = zb + (size_t)t * KC;
        zr[0]    = hi;
        zr[512]  = lo;
        zr[1024] = hi;
    }
}

// ---------------------------------------------------------------------------
// Host launcher
// ---------------------------------------------------------------------------
extern "C" void kernel_launch(void* const* d_in, const int* in_sizes, int n_in,
                              void* d_out, int out_size)
{
    const float* x     = (const float*)d_in[0];
    const float* A     = (const float*)d_in[1];
    const float* Dskip = (const float*)d_in[2];
    const float* WB    = (const float*)d_in[3];
    const float* bB    = (const float*)d_in[4];
    const float* WC    = (const float*)d_in[5];
    const float* bC    = (const float*)d_in[6];
    const float* Wdt   = (const float*)d_in[7];
    const float* bdt   = (const float*)d_in[8];
    const float* Wlin  = (const float*)d_in[9];
    const float* blin  = (const float*)d_in[10];
    const float* Wdec  = (const float*)d_in[11];
    const float* bdec  = (const float*)d_in[12];
    float* out = (float*)d_out;

    float *py, *pdt, *pbeff, *pbzero;
    __half *px0, *px1, *pwc;
    cudaGetSymbolAddress((void**)&py,     g_y);
    cudaGetSymbolAddress((void**)&pdt,    g_dt);
    cudaGetSymbolAddress((void**)&pbeff,  g_beff);
    cudaGetSymbolAddress((void**)&pbzero, g_bzero);
    cudaGetSymbolAddress((void**)&px0,    g_Xcat0);
    cudaGetSymbolAddress((void**)&px1,    g_Xcat1);
    cudaGetSymbolAddress((void**)&pwc,    g_Wcat);

    cudaFuncSetAttribute(tc_gemm<0>, cudaFuncAttributeMaxDynamicSharedMemorySize, TC_SMEM);
    cudaFuncSetAttribute(tc_gemm<1>, cudaFuncAttributeMaxDynamicSharedMemorySize, TC_SMEM);
    cudaFuncSetAttribute(tc_gemm<2>, cudaFuncAttributeMaxDynamicSharedMemorySize, TC_SMEM);

    const size_t WCSZ = (size_t)NW * KC;
    const size_t WSZ  = (size_t)DD * DD;

    dim3 tgrid(16, 16, 5), tblk(32, 8);
    dim3 t1grid(16, 16);
    tsplit_all_k<<<tgrid, tblk>>>(Wdt, Wlin, Wdec);     // slots 0,1,2,3,4 (4 = Wdec, temp)
    tsplit_bc_k<<<dim3(16, 2), tblk>>>(WB, WC);

    // --- Precompute fused decoder: F = Wlin2 @ Wdec (fp16 3-term), slot 4 ---
    // 1) split Wlin2 rows into Xcat0 (rows 0..511)
    splitx_k<<<(DD * DD / 4) / 256, 256>>>((const float4*)(Wlin + WSZ), px0);
    // 2) fused bias
    beff_k<<<2, 256>>>(blin + DD, Wdec, bdec);
    // 3) F = Wlin2 @ Wdec -> g_y (512x512 fp32), using Wdec slot 4
    tc_gemm<0><<<dim3(8, 4), 256, TC_SMEM>>>(px0, pwc + 4 * WCSZ, pbzero,
                                             nullptr, nullptr, py, nullptr);
    // 4) transpose+split F into slot 4 (overwrites Wdec split)
    tsplit_one_k<<<t1grid, tblk>>>(py, pwc + 4 * WCSZ);

    // --- Main pipeline ---
    dim3 gG1(NW / 64, MM / 128);   // (9, 32) fused dt+BC
    dim3 gG(DD / 64, MM / 128);    // (8, 32)
    dim3 gs(DD / 128, NCH, BB);

    splitx_k<<<(BLD / 4) / 256, 256>>>((const float4*)x, px0);

    // Layer 0
    tc_gemm<1><<<gG1, 256, TC_SMEM>>>(px0, pwc + 0 * WCSZ, bdt,
                                      bB, bC, pdt, nullptr);
    scan1_k<<<gs, 128>>>(x, A);
    scan2_k<<<(BB * DD * NN) / 256, 256>>>();
    scan3_k<<<gs, 128>>>(x, A, Dskip);
    tc_gemm<2><<<gG, 256, TC_SMEM>>>(px1, pwc + 2 * WCSZ, blin,
                                     nullptr, nullptr, py, px0);

    // Layer 1
    tc_gemm<1><<<gG1, 256, TC_SMEM>>>(px0, pwc + 1 * WCSZ, bdt + DD,
                                      bB + NN, bC + NN, pdt, nullptr);
    scan1_k<<<gs, 128>>>(py, A + (size_t)DD * NN);
    scan2_k<<<(BB * DD * NN) / 256, 256>>>();
    scan3_k<<<gs, 128>>>(py, A + (size_t)DD * NN, Dskip + DD);

    // Fused lin2+dec: out = z2 @ F + beff
    tc_gemm<0><<<gG, 256, TC_SMEM>>>(px1, pwc + 4 * WCSZ, pbeff,
                                     nullptr, nullptr, out, nullptr);
}

// round 11
// speedup vs baseline: 1.3992x; 1.0353x over previous
#include <cuda_runtime.h>
#include <cuda_fp16.h>
#include <math.h>
#include <cstdint>

// Problem constants
#define BB 4
#define LL 1024
#define DD 512
#define NN 16
#define OUTD 512
#define NLAYER 2
#define NCH 32
#define LCH 32

#define BLD (BB*LL*DD)
#define BLN (BB*LL*NN)
#define CHN (BB*NCH*DD*NN)

#define MM (BB*LL)      // 4096 rows
#define KC 1536         // concatenated K (3x512): [hi|lo|hi] x [hi|hi|lo]
#define NW 576          // widened N for fused dt+B+C gemm

// Scratch
__device__ float g_y[BLD];
__device__ float g_dt[BLD];
__device__ float g_Bm[BLN];
__device__ float g_Cm[BLN];
__device__ float g_P[CHN];
__device__ float g_He[CHN];
__device__ float g_carry[CHN];
__device__ float g_beff[DD];                      // fused decoder bias
__device__ float g_bzero[DD];                     // zero bias (zero-initialized)
__device__ __half g_Xcat0[(size_t)MM * KC];       // [Xh | Xl | Xh]
__device__ __half g_Xcat1[(size_t)MM * KC];       // z split
__device__ __half g_Wcat[5 * (size_t)NW * KC];    // [hi|hi|lo], transposed, 576-row slots

__device__ __forceinline__ float softplusf(float x) {
    return fmaxf(x, 0.f) + log1pf(__expf(-fabsf(x)));
}

__device__ __forceinline__ uint32_t smem_u32(const void* p) {
    uint32_t a;
    asm("{ .reg .u64 t; cvta.to.shared.u64 t, %1; cvt.u32.u64 %0, t; }" : "=r"(a) : "l"(p));
    return a;
}

// swizzled byte offset inside a 128B-row tile: r = row, c = 16B chunk in [0,8)
__device__ __forceinline__ uint32_t swz(int r, int c) {
    return ((uint32_t)r << 7) + ((uint32_t)(c ^ (r & 7)) << 4);
}

// ---------------------------------------------------------------------------
// fp16-input, fp32-acc HMMA GEMM (R8 configuration — best known).
// C[M, Ncols] = Xcat[M, KC] @ Wcat[Ncols, KC]^T  (TN)
// Tile 128(M) x 64(N), BK=64, 3-stage cp.async, 256 thr (4M x 2N warps).
// EPI 0: bias                          grid (Ncols/64, M/128)
// EPI 1: dt softplus + Bm/Cm fused     grid (9, 32)
// EPI 2: bias + fp16-split to xout     grid (8, 32)
// ---------------------------------------------------------------------------
#define BK 64
#define STG 3
#define ABYTES 16384
#define BBYTES 8192
#define STAGE_BYTES (ABYTES + BBYTES)
#define TC_SMEM (STG * STAGE_BYTES)

template<int EPI>
__global__ void __launch_bounds__(256, 3)
tc_gemm(const __half* __restrict__ A, const __half* __restrict__ Bw,
        const float* __restrict__ bias, const float* __restrict__ bB,
        const float* __restrict__ bC, float* __restrict__ C,
        __half* __restrict__ xout)
{
    extern __shared__ char smem[];
    uint32_t sbase = smem_u32(smem);

    int tid = threadIdx.x, wid = tid >> 5, lane = tid & 31;
    int bn = blockIdx.x * 64, bm = blockIdx.y * 128;
    int wm = wid & 3;           // m offset wm*32
    int wn = wid >> 2;          // n offset wn*32

    int lrow = ((lane >> 3) & 1) * 8 + (lane & 7);
    int lck = lane >> 4;
    uint32_t aoff[2][4], boff[2][4];
    #pragma unroll
    for (int mt = 0; mt < 2; mt++)
        #pragma unroll
        for (int ks = 0; ks < 4; ks++)
            aoff[mt][ks] = swz(wm * 32 + mt * 16 + lrow, ks * 2 + lck);
    #pragma unroll
    for (int nt = 0; nt < 2; nt++)
        #pragma unroll
        for (int ks = 0; ks < 4; ks++)
            boff[nt][ks] = ABYTES + swz(wn * 32 + nt * 16 + lrow, ks * 2 + lck);

    int ra = tid >> 1, ca0 = (tid & 1) * 4;
    int rb = tid >> 2, cb0 = (tid & 3) * 2;
    const __half* gA = A + (size_t)(bm + ra) * KC + ca0 * 8;
    const __half* gB = Bw + (size_t)(bn + rb) * KC + cb0 * 8;
    uint32_t dA[4], dB[2];
    #pragma unroll
    for (int i = 0; i < 4; i++) dA[i] = swz(ra, ca0 + i);
    #pragma unroll
    for (int i = 0; i < 2; i++) dB[i] = ABYTES + swz(rb, cb0 + i);

    float acc[2][4][4];
    #pragma unroll
    for (int i = 0; i < 2; i++)
        #pragma unroll
        for (int j = 0; j < 4; j++)
            #pragma unroll
            for (int q = 0; q < 4; q++) acc[i][j][q] = 0.f;

    const int NKB = KC / BK;    // 24

    #pragma unroll
    for (int s = 0; s < STG - 1; s++) {
        uint32_t st = sbase + s * STAGE_BYTES;
        int ko = s * BK;
        #pragma unroll
        for (int i = 0; i < 4; i++)
            asm volatile("cp.async.cg.shared.global [%0], [%1], 16;" :: "r"(st + dA[i]), "l"(gA + ko + i * 8));
        #pragma unroll
        for (int i = 0; i < 2; i++)
            asm volatile("cp.async.cg.shared.global [%0], [%1], 16;" :: "r"(st + dB[i]), "l"(gB + ko + i * 8));
        asm volatile("cp.async.commit_group;" ::: "memory");
    }

    uint32_t bufA[2][2][4], bufB[2][2][4];

    int sbuf = 0;
    for (int kb = 0; kb < NKB; kb++) {
        asm volatile("cp.async.wait_group %0;" :: "n"(STG - 2) : "memory");
        __syncthreads();

        int knext = kb + STG - 1;
        if (knext < NKB) {
            int sn = knext % STG;
            uint32_t st = sbase + sn * STAGE_BYTES;
            int ko = knext * BK;
            #pragma unroll
            for (int i = 0; i < 4; i++)
                asm volatile("cp.async.cg.shared.global [%0], [%1], 16;" :: "r"(st + dA[i]), "l"(gA + ko + i * 8));
            #pragma unroll
            for (int i = 0; i < 2; i++)
                asm volatile("cp.async.cg.shared.global [%0], [%1], 16;" :: "r"(st + dB[i]), "l"(gB + ko + i * 8));
        }
        asm volatile("cp.async.commit_group;" ::: "memory");

        uint32_t st = sbase + sbuf * STAGE_BYTES;

        // prime ks=0 operands
        #pragma unroll
        for (int mt = 0; mt < 2; mt++)
            asm volatile("ldmatrix.sync.aligned.m8n8.x4.shared.b16 {%0,%1,%2,%3}, [%4];"
                         : "=r"(bufA[0][mt][0]), "=r"(bufA[0][mt][1]),
                           "=r"(bufA[0][mt][2]), "=r"(bufA[0][mt][3])
                         : "r"(st + aoff[mt][0]));
        #pragma unroll
        for (int nt = 0; nt < 2; nt++)
            asm volatile("ldmatrix.sync.aligned.m8n8.x4.shared.b16 {%0,%1,%2,%3}, [%4];"
                         : "=r"(bufB[0][nt][0]), "=r"(bufB[0][nt][1]),
                           "=r"(bufB[0][nt][2]), "=r"(bufB[0][nt][3])
                         : "r"(st + boff[nt][0]));

        #pragma unroll
        for (int ks = 0; ks < 4; ks++) {
            int cb = ks & 1, nb = cb ^ 1;
            if (ks < 3) {
                #pragma unroll
                for (int mt = 0; mt < 2; mt++)
                    asm volatile("ldmatrix.sync.aligned.m8n8.x4.shared.b16 {%0,%1,%2,%3}, [%4];"
                                 : "=r"(bufA[nb][mt][0]), "=r"(bufA[nb][mt][1]),
                                   "=r"(bufA[nb][mt][2]), "=r"(bufA[nb][mt][3])
                                 : "r"(st + aoff[mt][ks + 1]));
                #pragma unroll
                for (int nt = 0; nt < 2; nt++)
                    asm volatile("ldmatrix.sync.aligned.m8n8.x4.shared.b16 {%0,%1,%2,%3}, [%4];"
                                 : "=r"(bufB[nb][nt][0]), "=r"(bufB[nb][nt][1]),
                                   "=r"(bufB[nb][nt][2]), "=r"(bufB[nb][nt][3])
                                 : "r"(st + boff[nt][ks + 1]));
            }
            #pragma unroll
            for (int mt = 0; mt < 2; mt++)
                #pragma unroll
                for (int nt = 0; nt < 2; nt++)
                    #pragma unroll
                    for (int nf = 0; nf < 2; nf++)
                        asm volatile(
                            "mma.sync.aligned.m16n8k16.row.col.f32.f16.f16.f32 "
                            "{%0,%1,%2,%3}, {%4,%5,%6,%7}, {%8,%9}, {%0,%1,%2,%3};"
                            : "+f"(acc[mt][nt * 2 + nf][0]), "+f"(acc[mt][nt * 2 + nf][1]),
                              "+f"(acc[mt][nt * 2 + nf][2]), "+f"(acc[mt][nt * 2 + nf][3])
                            : "r"(bufA[cb][mt][0]), "r"(bufA[cb][mt][1]),
                              "r"(bufA[cb][mt][2]), "r"(bufA[cb][mt][3]),
                              "r"(bufB[cb][nt][nf]), "r"(bufB[cb][nt][2 + nf]));
        }
        sbuf++;
        if (sbuf == STG) sbuf = 0;
    }

    // epilogue
    int mbase = bm + wm * 32 + (lane >> 2);
    int nbase = bn + wn * 32 + (lane & 3) * 2;
    #pragma unroll
    for (int mt = 0; mt < 2; mt++) {
        #pragma unroll
        for (int jf = 0; jf < 4; jf++) {
            int col = nbase + (jf >> 1) * 16 + (jf & 1) * 8;
            int m0 = mbase + mt * 16;
            float b0, b1;
            if (EPI == 1 && col >= 512) {
                if (col < 528)      { b0 = bB[col - 512]; b1 = bB[col - 511]; }
                else if (col < 544) { b0 = bC[col - 528]; b1 = bC[col - 527]; }
                else                { b0 = 0.f; b1 = 0.f; }
            } else {
                b0 = bias[col]; b1 = bias[col + 1];
            }
            float v0 = acc[mt][jf][0] + b0, v1 = acc[mt][jf][1] + b1;
            float v2 = acc[mt][jf][2] + b0, v3 = acc[mt][jf][3] + b1;

            if (EPI == 1 && col >= 512) {
                if (col < 528) {
                    int n = col - 512;
                    *(float2*)(g_Bm + (size_t)m0 * NN + n)       = make_float2(v0, v1);
                    *(float2*)(g_Bm + (size_t)(m0 + 8) * NN + n) = make_float2(v2, v3);
                } else if (col < 544) {
                    int n = col - 528;
                    *(float2*)(g_Cm + (size_t)m0 * NN + n)       = make_float2(v0, v1);
                    *(float2*)(g_Cm + (size_t)(m0 + 8) * NN + n) = make_float2(v2, v3);
                }
                continue;
            }
            if (EPI == 1) { v0 = softplusf(v0); v1 = softplusf(v1); v2 = softplusf(v2); v3 = softplusf(v3); }
            *(float2*)(C + (size_t)m0 * DD + col)       = make_float2(v0, v1);
            *(float2*)(C + (size_t)(m0 + 8) * DD + col) = make_float2(v2, v3);
            if (EPI == 2) {
                __half h0 = __float2half_rn(v0), h1 = __float2half_rn(v1);
                __half h2 = __float2half_rn(v2), h3 = __float2half_rn(v3);
                __half2 hv0(h0, h1), hv1(h2, h3);
                __half2 lv0(__float2half_rn(v0 - __half2float(h0)),
                            __float2half_rn(v1 - __half2float(h1)));
                __half2 lv1(__float2half_rn(v2 - __half2float(h2)),
                            __float2half_rn(v3 - __half2float(h3)));
                __half* r0 = xout + (size_t)m0 * KC + col;
                __half* r1 = xout + (size_t)(m0 + 8) * KC + col;
                *(__half2*)(r0)        = hv0;
                *(__half2*)(r0 + 512)  = lv0;
                *(__half2*)(r0 + 1024) = hv0;
                *(__half2*)(r1)        = hv1;
                *(__half2*)(r1 + 512)  = lv1;
                *(__half2*)(r1 + 1024) = hv1;
            }
        }
    }
}

// ---------------------------------------------------------------------------
// Activation split: float [M][512] -> out fp16 [M][1536] = [hi|lo|hi]
// ---------------------------------------------------------------------------
__global__ void splitx_k(const float4* __restrict__ in, __half* __restrict__ out)
{
    int i = blockIdx.x * blockDim.x + threadIdx.x;
    int m = i >> 7;
    int k4 = (i & 127) << 2;
    float4 v = in[i];
    __half2 h0(__float2half_rn(v.x), __float2half_rn(v.y));
    __half2 h1(__float2half_rn(v.z), __float2half_rn(v.w));
    __half2 l0(__float2half_rn(v.x - __half2float(h0.x)),
               __float2half_rn(v.y - __half2float(h0.y)));
    __half2 l1(__float2half_rn(v.z - __half2float(h1.x)),
               __float2half_rn(v.w - __half2float(h1.y)));
    __half* row = out + (size_t)m * KC;
    *(__half2*)(row + k4)        = h0;
    *(__half2*)(row + k4 + 2)    = h1;
    *(__half2*)(row + k4 + 512)  = l0;
    *(__half2*)(row + k4 + 514)  = l1;
    *(__half2*)(row + k4 + 1024) = h0;
    *(__half2*)(row + k4 + 1026) = h1;
}

// ---------------------------------------------------------------------------
// Big-weight transpose+split. blockIdx.z = slot.
// slots: 0,1 = Wdt layers; 2 = Wlin layer 0; 3 = Wlin layer 1 (unused); 4 = Wdec
// ---------------------------------------------------------------------------
__global__ void tsplit_all_k(const float* __restrict__ Wdt, const float* __restrict__ Wlin,
                             const float* __restrict__ Wdec)
{
    __shared__ float t[32][33];
    int slot = blockIdx.z;
    const float* W = (slot == 0) ? Wdt
                   : (slot == 1) ? Wdt + (size_t)DD * DD
                   : (slot == 2) ? Wlin
                   : (slot == 3) ? Wlin + (size_t)DD * DD
                                 : Wdec;
    __half* out = g_Wcat + (size_t)slot * NW * KC;

    int bk = blockIdx.x * 32, bn = blockIdx.y * 32;
    int tx = threadIdx.x, ty = threadIdx.y;
    #pragma unroll
    for (int i = 0; i < 32; i += 8)
        t[ty + i][tx] = W[(size_t)(bk + ty + i) * DD + bn + tx];
    __syncthreads();
    #pragma unroll
    for (int i = 0; i < 32; i += 8) {
        float v = t[tx][ty + i];
        __half h = __float2half_rn(v);
        __half l = __float2half_rn(v - __half2float(h));
        size_t o = (size_t)(bn + ty + i) * KC + bk + tx;
        out[o]        = h;
        out[o + 512]  = h;
        out[o + 1024] = l;
    }
}

// Single-slot transpose+split (for the fused decoder weight F in g_y).
__global__ void tsplit_one_k(const float* __restrict__ W, __half* __restrict__ out)
{
    __shared__ float t[32][33];
    int bk = blockIdx.x * 32, bn = blockIdx.y * 32;
    int tx = threadIdx.x, ty = threadIdx.y;
    #pragma unroll
    for (int i = 0; i < 32; i += 8)
        t[ty + i][tx] = W[(size_t)(bk + ty + i) * DD + bn + tx];
    __syncthreads();
    #pragma unroll
    for (int i = 0; i < 32; i += 8) {
        float v = t[tx][ty + i];
        __half h = __float2half_rn(v);
        __half l = __float2half_rn(v - __half2float(h));
        size_t o = (size_t)(bn + ty + i) * KC + bk + tx;
        out[o]        = h;
        out[o + 512]  = h;
        out[o + 1024] = l;
    }
}

// ---------------------------------------------------------------------------
// WB/WC transpose+split into rows 512..575 of dt slots.
// ---------------------------------------------------------------------------
__global__ void tsplit_bc_k(const float* __restrict__ WB, const float* __restrict__ WC)
{
    int l = blockIdx.y;
    int bk = blockIdx.x * 32;
    int tx = threadIdx.x;
    __half* out = g_Wcat + (size_t)l * NW * KC + (size_t)512 * KC;

    for (int r = threadIdx.y; r < 64; r += 8) {
        float v = 0.f;
        if (r < 16)      v = WB[(size_t)l * DD * NN + (size_t)(bk + tx) * NN + r];
        else if (r < 32) v = WC[(size_t)l * DD * NN + (size_t)(bk + tx) * NN + (r - 16)];
        __half h = __float2half_rn(v);
        __half lo = __float2half_rn(v - __half2float(h));
        size_t o = (size_t)r * KC + bk + tx;
        out[o]        = h;
        out[o + 512]  = h;
        out[o + 1024] = lo;
    }
}

// ---------------------------------------------------------------------------
// Fused decoder bias: beff[o] = bdec[o] + sum_d blin2[d] * Wdec[d][o]
// grid 16, block 256: each block -> 32 outputs, 8 warps reduce 64 d's each.
// ---------------------------------------------------------------------------
__global__ void beff_k(const float* __restrict__ blin2, const float* __restrict__ Wdec,
                       const float* __restrict__ bdec)
{
    __shared__ float part[8][32];
    int og = threadIdx.x & 31;
    int r  = threadIdx.x >> 5;
    int o  = blockIdx.x * 32 + og;
    float acc = 0.f;
    int d0 = r * 64;
    #pragma unroll 8
    for (int d = d0; d < d0 + 64; d++)
        acc = fmaf(blin2[d], Wdec[(size_t)d * DD + o], acc);
    part[r][og] = acc;
    __syncthreads();
    if (r == 0) {
        float s = bdec[o];
        #pragma unroll
        for (int i = 0; i < 8; i++) s += part[i][og];
        g_beff[o] = s;
    }
}

// ---------------------------------------------------------------------------
// Scan pass 1: local chunk scan from zero; store P, He.
// grid = (4, NCH, 4), block 128
// ---------------------------------------------------------------------------
__global__ void scan1_k(const float* __restrict__ yin, const float* __restrict__ A)
{
    __shared__ float sB[LCH * NN];
    int d = blockIdx.x * 128 + threadIdx.x;
    int c = blockIdx.y, b = blockIdx.z;
    int t0 = c * LCH;

    const float4* src = (const float4*)(g_Bm + ((size_t)b * LL + t0) * NN);
    #pragma unroll
    for (int i = threadIdx.x; i < LCH * NN / 4; i += 128)
        ((float4*)sB)[i] = src[i];
    __syncthreads();

    float av[NN], h[NN], p[NN];
    #pragma unroll
    for (int q = 0; q < 4; q++)
        *(float4*)(av + q * 4) = *(const float4*)(A + (size_t)d * NN + q * 4);
    #pragma unroll
    for (int n = 0; n < NN; n++) { h[n] = 0.f; p[n] = 1.f; }

    const float* dtp = g_dt + ((size_t)b * LL + t0) * DD + d;
    const float* yp  = yin  + ((size_t)b * LL + t0) * DD + d;

    for (int t = 0; t < LCH; t++) {
        float dv = dtp[(size_t)t * DD];
        float u  = dv * yp[(size_t)t * DD];
        #pragma unroll
        for (int n = 0; n < NN; n++) {
            float e = __expf(dv * av[n]);
            p[n] *= e;
            h[n] = fmaf(e, h[n], u * sB[t * NN + n]);
        }
    }

    size_t o = (((size_t)b * NCH + c) * DD + d) * NN;
    #pragma unroll
    for (int q = 0; q < 4; q++) {
        *(float4*)(g_P  + o + q * 4) = *(float4*)(p + q * 4);
        *(float4*)(g_He + o + q * 4) = *(float4*)(h + q * 4);
    }
}

// ---------------------------------------------------------------------------
// Scan pass 2 (batched loads across NCH chunks)
// ---------------------------------------------------------------------------
__global__ void scan2_k()
{
    int tid = blockIdx.x * blockDim.x + threadIdx.x;
    int b  = tid >> 13;
    int dn = tid & 8191;
    size_t base = (size_t)b * NCH * DD * NN + dn;

    float p[NCH], he[NCH];
    #pragma unroll
    for (int c = 0; c < NCH; c++) {
        p[c]  = g_P [base + (size_t)c * DD * NN];
        he[c] = g_He[base + (size_t)c * DD * NN];
    }
    float hc = 0.f;
    float cr[NCH];
    #pragma unroll
    for (int c = 0; c < NCH; c++) {
        cr[c] = hc;
        hc = fmaf(p[c], hc, he[c]);
    }
    #pragma unroll
    for (int c = 0; c < NCH; c++)
        g_carry[base + (size_t)c * DD * NN] = cr[c];
}

// ---------------------------------------------------------------------------
// Scan pass 3: rescan with carry; write z as fp16 split into Xcat1.
// grid = (4, NCH, 4), block 128
// ---------------------------------------------------------------------------
__global__ void scan3_k(const float* __restrict__ yin, const float* __restrict__ A,
                        const float* __restrict__ Dskip)
{
    __shared__ float sB[LCH * NN];
    __shared__ float sC[LCH * NN];
    int d = blockIdx.x * 128 + threadIdx.x;
    int c = blockIdx.y, b = blockIdx.z;
    int t0 = c * LCH;

    {
        const float4* srcB = (const float4*)(g_Bm + ((size_t)b * LL + t0) * NN);
        const float4* srcC = (const float4*)(g_Cm + ((size_t)b * LL + t0) * NN);
        #pragma unroll
        for (int i = threadIdx.x; i < LCH * NN / 4; i += 128) {
            ((float4*)sB)[i] = srcB[i];
            ((float4*)sC)[i] = srcC[i];
        }
    }
    __syncthreads();

    float av[NN], h[NN];
    #pragma unroll
    for (int q = 0; q < 4; q++)
        *(float4*)(av + q * 4) = *(const float4*)(A + (size_t)d * NN + q * 4);
    size_t co = (((size_t)b * NCH + c) * DD + d) * NN;
    #pragma unroll
    for (int q = 0; q < 4; q++)
        *(float4*)(h + q * 4) = *(const float4*)(g_carry + co + q * 4);

    float ds = Dskip[d];
    const float* dtp = g_dt + ((size_t)b * LL + t0) * DD + d;
    const float* yp  = yin  + ((size_t)b * LL + t0) * DD + d;
    __half* zb = g_Xcat1 + ((size_t)b * LL + t0) * KC + d;

    for (int t = 0; t < LCH; t++) {
        float dv = dtp[(size_t)t * DD];
        float yv = yp[(size_t)t * DD];
        float u  = dv * yv;
        float acc = 0.f;
        #pragma unroll
        for (int n = 0; n < NN; n++) {
            float e = __expf(dv * av[n]);
            h[n] = fmaf(e, h[n], u * sB[t * NN + n]);
            acc = fmaf(h[n], sC[t * NN + n], acc);
        }
        float z = fmaxf(fmaf(ds, yv, acc), 0.f);
        __half hi = __float2half_rn(z);
        __half lo = __float2half_rn(z - __half2float(hi));
        __half* zr = zb + (size_t)t * KC;
        zr[0]    = hi;
        zr[512]  = lo;
        zr[1024] = hi;
    }
}

// ---------------------------------------------------------------------------
// Host launcher
// ---------------------------------------------------------------------------
extern "C" void kernel_launch(void* const* d_in, const int* in_sizes, int n_in,
                              void* d_out, int out_size)
{
    const float* x     = (const float*)d_in[0];
    const float* A     = (const float*)d_in[1];
    const float* Dskip = (const float*)d_in[2];
    const float* WB    = (const float*)d_in[3];
    const float* bB    = (const float*)d_in[4];
    const float* WC    = (const float*)d_in[5];
    const float* bC    = (const float*)d_in[6];
    const float* Wdt   = (const float*)d_in[7];
    const float* bdt   = (const float*)d_in[8];
    const float* Wlin  = (const float*)d_in[9];
    const float* blin  = (const float*)d_in[10];
    const float* Wdec  = (const float*)d_in[11];
    const float* bdec  = (const float*)d_in[12];
    float* out = (float*)d_out;

    float *py, *pdt, *pbeff, *pbzero;
    __half *px0, *px1, *pwc;
    cudaGetSymbolAddress((void**)&py,     g_y);
    cudaGetSymbolAddress((void**)&pdt,    g_dt);
    cudaGetSymbolAddress((void**)&pbeff,  g_beff);
    cudaGetSymbolAddress((void**)&pbzero, g_bzero);
    cudaGetSymbolAddress((void**)&px0,    g_Xcat0);
    cudaGetSymbolAddress((void**)&px1,    g_Xcat1);
    cudaGetSymbolAddress((void**)&pwc,    g_Wcat);

    cudaFuncSetAttribute(tc_gemm<0>, cudaFuncAttributeMaxDynamicSharedMemorySize, TC_SMEM);
    cudaFuncSetAttribute(tc_gemm<1>, cudaFuncAttributeMaxDynamicSharedMemorySize, TC_SMEM);
    cudaFuncSetAttribute(tc_gemm<2>, cudaFuncAttributeMaxDynamicSharedMemorySize, TC_SMEM);

    const size_t WCSZ = (size_t)NW * KC;
    const size_t WSZ  = (size_t)DD * DD;

    dim3 tgrid(16, 16, 5), tblk(32, 8);
    dim3 t1grid(16, 16);
    tsplit_all_k<<<tgrid, tblk>>>(Wdt, Wlin, Wdec);     // slots 0,1,2,3,4 (4 = Wdec, temp)
    tsplit_bc_k<<<dim3(16, 2), tblk>>>(WB, WC);

    // --- Precompute fused decoder: F = Wlin2 @ Wdec (fp16 3-term), slot 4 ---
    splitx_k<<<(DD * DD / 4) / 256, 256>>>((const float4*)(Wlin + WSZ), px0);
    beff_k<<<16, 256>>>(blin + DD, Wdec, bdec);
    tc_gemm<0><<<dim3(8, 4), 256, TC_SMEM>>>(px0, pwc + 4 * WCSZ, pbzero,
                                             nullptr, nullptr, py, nullptr);
    tsplit_one_k<<<t1grid, tblk>>>(py, pwc + 4 * WCSZ);

    // --- Main pipeline ---
    dim3 gG1(NW / 64, MM / 128);   // (9, 32) fused dt+BC
    dim3 gG(DD / 64, MM / 128);    // (8, 32)
    dim3 gs(DD / 128, NCH, BB);

    splitx_k<<<(BLD / 4) / 256, 256>>>((const float4*)x, px0);

    // Layer 0
    tc_gemm<1><<<gG1, 256, TC_SMEM>>>(px0, pwc + 0 * WCSZ, bdt,
                                      bB, bC, pdt, nullptr);
    scan1_k<<<gs, 128>>>(x, A);
    scan2_k<<<(BB * DD * NN) / 256, 256>>>();
    scan3_k<<<gs, 128>>>(x, A, Dskip);
    tc_gemm<2><<<gG, 256, TC_SMEM>>>(px1, pwc + 2 * WCSZ, blin,
                                     nullptr, nullptr, py, px0);

    // Layer 1
    tc_gemm<1><<<gG1, 256, TC_SMEM>>>(px0, pwc + 1 * WCSZ, bdt + DD,
                                      bB + NN, bC + NN, pdt, nullptr);
    scan1_k<<<gs, 128>>>(py, A + (size_t)DD * NN);
    scan2_k<<<(BB * DD * NN) / 256, 256>>>();
    scan3_k<<<gs, 128>>>(py, A + (size_t)DD * NN, Dskip + DD);

    // Fused lin2+dec: out = z2 @ F + beff
    tc_gemm<0><<<gG, 256, TC_SMEM>>>(px1, pwc + 4 * WCSZ, pbeff,
                                     nullptr, nullptr, out, nullptr);
}